// round 11
// baseline (speedup 1.0000x reference)
#include <cuda_runtime.h>
#include <cuda.h>
#include <cstdint>

// LIF layer scan: B=64, F=256, L=2048.  out = [z | s], each B*F*L float32.
//
// Balanced persistent TMA kernel, fine-grained pipeline (CHUNK=32):
//   grid=148 (1 CTA/SM); blocks 0..103 own 111 rows, 104..147 own 110
//   (104*111+44*110=16384). Dual tensor maps (box height 111/110), no OOB.
// Per chunk: 1 UTMALDG (14KB, 4-stage ring, tx-mbarrier) + scan (8 float4/row)
// + 1 z UTMASTG + 1 s UTMASTG (4-slot ring, bulk_group, wait_group 3).
// SMEM tile bases 1024-aligned (TILE_STRIDE=14336) so SW128 hardware swizzle
// matches the in-kernel quad^(r&7) formula.

#define BB 64
#define FF 256
#define LL 2048
#define CHUNK 32
#define NTH 128
#define NCH (LL / CHUNK)     // 64
#define NBIG 104

#define BETA 15.0f
#define DT 1.0f

#define TILE_STRIDE 14336                 // 111*128=14208 padded to 14*1024
#define BARB(s) ((s) * 8)
#define IN_OFF  1024
#define ST_OFF  (IN_OFF + 4 * TILE_STRIDE)        // 1024 + 57344 = 58368
#define ST_SLOT (2 * TILE_STRIDE)                 // z tile + s tile
#define SMEM_BYTES (ST_OFF + 4 * ST_SLOT)         // 173056

__device__ __forceinline__ void mbar_init(uint32_t a, uint32_t c) {
    asm volatile("mbarrier.init.shared.b64 [%0], %1;" :: "r"(a), "r"(c) : "memory");
}
__device__ __forceinline__ void mbar_expect_tx(uint32_t a, uint32_t bytes) {
    asm volatile("mbarrier.arrive.expect_tx.shared.b64 _, [%0], %1;"
                 :: "r"(a), "r"(bytes) : "memory");
}
__device__ __forceinline__ void mbar_wait(uint32_t a, uint32_t parity) {
    asm volatile(
        "{\n\t.reg .pred P;\n\t"
        "WL_%=:\n\t"
        "mbarrier.try_wait.parity.acquire.cta.shared::cta.b64 P, [%0], %1, 0x989680;\n\t"
        "@P bra.uni WD_%=;\n\t"
        "bra.uni WL_%=;\n\t"
        "WD_%=:\n\t}"
        :: "r"(a), "r"(parity) : "memory");
}
__device__ __forceinline__ void tma_load_2d(uint32_t smem, const CUtensorMap* m,
                                            int x, int y, uint32_t bar) {
    asm volatile(
        "cp.async.bulk.tensor.2d.shared::cta.global.tile.mbarrier::complete_tx::bytes "
        "[%0], [%1, {%2, %3}], [%4];"
        :: "r"(smem), "l"(m), "r"(x), "r"(y), "r"(bar) : "memory");
}
__device__ __forceinline__ void tma_store_2d(const CUtensorMap* m,
                                             int x, int y, uint32_t smem) {
    asm volatile(
        "cp.async.bulk.tensor.2d.global.shared::cta.tile.bulk_group "
        "[%0, {%1, %2}], [%3];"
        :: "l"(m), "r"(x), "r"(y), "r"(smem) : "memory");
}

__global__ __launch_bounds__(NTH, 1)
void lif_tma_kernel(const __grid_constant__ CUtensorMap tin_a,
                    const __grid_constant__ CUtensorMap tin_b,
                    const __grid_constant__ CUtensorMap tz_a,
                    const __grid_constant__ CUtensorMap tz_b,
                    const __grid_constant__ CUtensorMap ts_a,
                    const __grid_constant__ CUtensorMap ts_b,
                    const float* __restrict__ raw_tau,
                    const float* __restrict__ thr_p)
{
    extern __shared__ char smem[];
    uint32_t sb;
    asm("{ .reg .u64 t; cvta.to.shared.u64 t, %1; cvt.u32.u64 %0, t; }"
        : "=r"(sb) : "l"(smem));

    const int tid = threadIdx.x;
    const int bid = blockIdx.x;
    const bool big = (bid < NBIG);
    const int H = big ? 111 : 110;
    const int row0 = big ? bid * 111 : NBIG * 111 + (bid - NBIG) * 110;
    const CUtensorMap* tin = big ? &tin_a : &tin_b;
    const CUtensorMap* tz  = big ? &tz_a  : &tz_b;
    const CUtensorMap* tsm = big ? &ts_a  : &ts_b;
    const uint32_t tx_bytes = (uint32_t)H * 128;   // one tile: H rows x 128B

    const float thr = thr_p[0];
    const bool active = (tid < H);
    float alpha = 0.0f, one_m_alpha = 0.0f;
    if (active) {
        float rt = raw_tau[(row0 + tid) % FF];
        float sp = fmaxf(rt, 0.0f) + log1pf(expf(-fabsf(rt)));  // stable softplus
        float tau = sp + 1e-4f;
        alpha = expf(-DT / tau);
        one_m_alpha = 1.0f - alpha;
    }
    const float beta_thr = BETA * thr;

    if (tid == 0) {
        #pragma unroll
        for (int s = 0; s < 4; s++) mbar_init(sb + BARB(s), 1);
    }
    __syncthreads();

    // prologue: input stages 0..3
    if (tid == 0) {
        #pragma unroll
        for (int s = 0; s < 4; s++) {
            mbar_expect_tx(sb + BARB(s), tx_bytes);
            tma_load_2d(sb + IN_OFF + s * TILE_STRIDE, tin, s * CHUNK, row0,
                        sb + BARB(s));
        }
    }

    const int sw = tid & 7;
    const uint32_t rbase = (uint32_t)tid * 128;
    float vv = 0.0f;

    for (int k = 0; k < NCH; k++) {
        const int si = k & 3;
        mbar_wait(sb + BARB(si), (k >> 2) & 1);

        if (active) {
            const char* ib = smem + IN_OFF + si * TILE_STRIDE + rbase;
            char* zt = smem + ST_OFF + si * ST_SLOT + rbase;
            char* st = zt + TILE_STRIDE;
            #pragma unroll
            for (int tb = 0; tb < 8; tb++) {
                const uint32_t off = (uint32_t)(tb ^ sw) << 4;
                float4 in4 = *(const float4*)(ib + off);          // LDS.128
                float4 z4, s4;
                float v_pre; bool spk;
                v_pre = fmaf(alpha, vv, one_m_alpha * in4.x);
                z4.x = fmaf(BETA, v_pre, -beta_thr);
                spk = (v_pre >= thr); s4.x = spk ? 1.0f : 0.0f; vv = spk ? 0.0f : v_pre;
                v_pre = fmaf(alpha, vv, one_m_alpha * in4.y);
                z4.y = fmaf(BETA, v_pre, -beta_thr);
                spk = (v_pre >= thr); s4.y = spk ? 1.0f : 0.0f; vv = spk ? 0.0f : v_pre;
                v_pre = fmaf(alpha, vv, one_m_alpha * in4.z);
                z4.z = fmaf(BETA, v_pre, -beta_thr);
                spk = (v_pre >= thr); s4.z = spk ? 1.0f : 0.0f; vv = spk ? 0.0f : v_pre;
                v_pre = fmaf(alpha, vv, one_m_alpha * in4.w);
                z4.w = fmaf(BETA, v_pre, -beta_thr);
                spk = (v_pre >= thr); s4.w = spk ? 1.0f : 0.0f; vv = spk ? 0.0f : v_pre;
                *(float4*)(zt + off) = z4;                        // STS.128
                *(float4*)(st + off) = s4;                        // STS.128
            }
        }
        __syncthreads();   // z/s tiles complete; input stage si consumed

        if (tid == 0) {
            // refill input stage si (chunk k+4)
            if (k + 4 < NCH) {
                mbar_expect_tx(sb + BARB(si), tx_bytes);
                tma_load_2d(sb + IN_OFF + si * TILE_STRIDE, tin,
                            (k + 4) * CHUNK, row0, sb + BARB(si));
            }
            asm volatile("fence.proxy.async.shared::cta;" ::: "memory");
            const int t0 = k * CHUNK;
            const uint32_t slot = sb + ST_OFF + si * ST_SLOT;
            tma_store_2d(tz,  t0, row0, slot);
            tma_store_2d(tsm, t0, row0, slot + TILE_STRIDE);
            asm volatile("cp.async.bulk.commit_group;" ::: "memory");
            // slot reused 4 chunks from now: allow 3 groups in flight
            asm volatile("cp.async.bulk.wait_group 3;" ::: "memory");
        }
        __syncthreads();
    }

    if (tid == 0)
        asm volatile("cp.async.bulk.wait_group 0;" ::: "memory");
}

// ---------------- host side ----------------

typedef CUresult (*EncodeFn)(CUtensorMap*, CUtensorMapDataType, cuuint32_t, void*,
                             const cuuint64_t*, const cuuint64_t*,
                             const cuuint32_t*, const cuuint32_t*,
                             CUtensorMapInterleave, CUtensorMapSwizzle,
                             CUtensorMapL2promotion, CUtensorMapFloatOOBfill);

static void make_map(EncodeFn enc, CUtensorMap* m, void* base, unsigned H) {
    cuuint64_t dims[2]    = {LL, (cuuint64_t)BB * FF};
    cuuint64_t strides[1] = {LL * sizeof(float)};
    cuuint32_t box[2]     = {32, H};
    cuuint32_t es[2]      = {1, 1};
    enc(m, CU_TENSOR_MAP_DATA_TYPE_FLOAT32, 2, base, dims, strides, box, es,
        CU_TENSOR_MAP_INTERLEAVE_NONE, CU_TENSOR_MAP_SWIZZLE_128B,
        CU_TENSOR_MAP_L2_PROMOTION_L2_128B, CU_TENSOR_MAP_FLOAT_OOB_FILL_NONE);
}

extern "C" void kernel_launch(void* const* d_in, const int* in_sizes, int n_in,
                              void* d_out, int out_size)
{
    float* I             = (float*)d_in[0];
    const float* raw_tau = (const float*)d_in[1];
    const float* thr     = (const float*)d_in[2];
    float* out           = (float*)d_out;

    static EncodeFn enc = nullptr;
    if (!enc) {
        cudaDriverEntryPointQueryResult qr;
        void* fp = nullptr;
        cudaGetDriverEntryPoint("cuTensorMapEncodeTiled", &fp,
                                cudaEnableDefault, &qr);
        enc = (EncodeFn)fp;
        cudaFuncSetAttribute(lif_tma_kernel,
                             cudaFuncAttributeMaxDynamicSharedMemorySize, SMEM_BYTES);
    }
    if (!enc) return;

    float* sbase = out + (size_t)BB * FF * LL;
    CUtensorMap in_a, in_b, z_a, z_b, s_a, s_b;
    make_map(enc, &in_a, I, 111);     make_map(enc, &in_b, I, 110);
    make_map(enc, &z_a,  out, 111);   make_map(enc, &z_b,  out, 110);
    make_map(enc, &s_a,  sbase, 111); make_map(enc, &s_b,  sbase, 110);

    lif_tma_kernel<<<148, NTH, SMEM_BYTES>>>(in_a, in_b, z_a, z_b, s_a, s_b,
                                             raw_tau, thr);
}

// round 12
// speedup vs baseline: 1.0625x; 1.0625x over previous
#include <cuda_runtime.h>
#include <cuda.h>
#include <cstdint>

// LIF layer scan: B=64, F=256, L=2048.  out = [z | s], each B*F*L float32.
//
// Warp-specialized barrier-free pipeline, grid=148 (1 CTA/SM), 160 threads:
//   tid 0..127 : scan threads (H=111/110 active), one row each
//   tid 128    : TMA-issue thread (loads + stores + ring bookkeeping)
// Handshakes: IN_FULL (tx-mbarrier), IN_EMPTY / ST_FULL (count=128, scan),
// ST_FREE (count=1, TMA thread after wait_group drain; pre-armed at startup).
// Balanced rows: blocks 0..103 own 111, 104..147 own 110 (=16384). Dual maps.
// SMEM tile bases 1024-aligned (TILE_STRIDE=14336) so the SW128 hardware
// swizzle matches the in-kernel quad^(r&7) formula.

#define BB 64
#define FF 256
#define LL 2048
#define CHUNK 64
#define NTH 160
#define NCH (LL / CHUNK)     // 32
#define NBIG 104

#define BETA 15.0f
#define DT 1.0f

#define TILE_STRIDE 14336
#define IN_STG  (2 * TILE_STRIDE)
#define ST_SLOT (4 * TILE_STRIDE)
// barrier offsets
#define B_INF(s)  ((s) * 8)          // IN_FULL
#define B_INE(s)  (16 + (s) * 8)     // IN_EMPTY
#define B_STF(s)  (32 + (s) * 8)     // ST_FULL
#define B_STE(s)  (48 + (s) * 8)     // ST_FREE
#define IN_OFF  1024
#define ST_OFF  (IN_OFF + 2 * IN_STG)       // 58368
#define SMEM_BYTES (ST_OFF + 2 * ST_SLOT)   // 173056

__device__ __forceinline__ void mbar_init(uint32_t a, uint32_t c) {
    asm volatile("mbarrier.init.shared.b64 [%0], %1;" :: "r"(a), "r"(c) : "memory");
}
__device__ __forceinline__ void mbar_arrive(uint32_t a) {
    asm volatile("mbarrier.arrive.release.cta.shared::cta.b64 _, [%0];"
                 :: "r"(a) : "memory");
}
__device__ __forceinline__ void mbar_expect_tx(uint32_t a, uint32_t bytes) {
    asm volatile("mbarrier.arrive.expect_tx.shared.b64 _, [%0], %1;"
                 :: "r"(a), "r"(bytes) : "memory");
}
__device__ __forceinline__ void mbar_wait(uint32_t a, uint32_t parity) {
    asm volatile(
        "{\n\t.reg .pred P;\n\t"
        "WL_%=:\n\t"
        "mbarrier.try_wait.parity.acquire.cta.shared::cta.b64 P, [%0], %1, 0x989680;\n\t"
        "@P bra.uni WD_%=;\n\t"
        "bra.uni WL_%=;\n\t"
        "WD_%=:\n\t}"
        :: "r"(a), "r"(parity) : "memory");
}
__device__ __forceinline__ void tma_load_2d(uint32_t smem, const CUtensorMap* m,
                                            int x, int y, uint32_t bar) {
    asm volatile(
        "cp.async.bulk.tensor.2d.shared::cta.global.tile.mbarrier::complete_tx::bytes "
        "[%0], [%1, {%2, %3}], [%4];"
        :: "r"(smem), "l"(m), "r"(x), "r"(y), "r"(bar) : "memory");
}
__device__ __forceinline__ void tma_store_2d(const CUtensorMap* m,
                                             int x, int y, uint32_t smem) {
    asm volatile(
        "cp.async.bulk.tensor.2d.global.shared::cta.tile.bulk_group "
        "[%0, {%1, %2}], [%3];"
        :: "l"(m), "r"(x), "r"(y), "r"(smem) : "memory");
}

__global__ __launch_bounds__(NTH, 1)
void lif_tma_kernel(const __grid_constant__ CUtensorMap tin_a,
                    const __grid_constant__ CUtensorMap tin_b,
                    const __grid_constant__ CUtensorMap tz_a,
                    const __grid_constant__ CUtensorMap tz_b,
                    const __grid_constant__ CUtensorMap ts_a,
                    const __grid_constant__ CUtensorMap ts_b,
                    const float* __restrict__ raw_tau,
                    const float* __restrict__ thr_p)
{
    extern __shared__ char smem[];
    uint32_t sb;
    asm("{ .reg .u64 t; cvta.to.shared.u64 t, %1; cvt.u32.u64 %0, t; }"
        : "=r"(sb) : "l"(smem));

    const int tid = threadIdx.x;
    const int bid = blockIdx.x;
    const bool big = (bid < NBIG);
    const int H = big ? 111 : 110;
    const int row0 = big ? bid * 111 : NBIG * 111 + (bid - NBIG) * 110;
    const CUtensorMap* tin = big ? &tin_a : &tin_b;
    const CUtensorMap* tz  = big ? &tz_a  : &tz_b;
    const CUtensorMap* tsm = big ? &ts_a  : &ts_b;
    const uint32_t tx_bytes = (uint32_t)H * 256;

    if (tid == 0) {
        #pragma unroll
        for (int s = 0; s < 2; s++) {
            mbar_init(sb + B_INF(s), 1);
            mbar_init(sb + B_INE(s), 128);
            mbar_init(sb + B_STF(s), 128);
            mbar_init(sb + B_STE(s), 1);
        }
    }
    __syncthreads();   // barrier init visible; only sync in the kernel

    if (tid < 128) {
        // ===================== scan threads =====================
        const float thr = thr_p[0];
        const bool active = (tid < H);
        float alpha = 0.0f, one_m_alpha = 0.0f;
        if (active) {
            float rt = raw_tau[(row0 + tid) % FF];
            float sp = fmaxf(rt, 0.0f) + log1pf(expf(-fabsf(rt)));
            float tau = sp + 1e-4f;
            alpha = expf(-DT / tau);
            one_m_alpha = 1.0f - alpha;
        }
        const float beta_thr = BETA * thr;
        const int sw = tid & 7;
        const uint32_t rbase = (uint32_t)tid * 128;
        float vv = 0.0f;

        for (int k = 0; k < NCH; k++) {
            const int si = k & 1;
            const uint32_t par = (k >> 1) & 1;
            mbar_wait(sb + B_INF(si), par);   // input stage ready
            mbar_wait(sb + B_STE(si), par);   // store slot drained (pre-armed)

            if (active) {
                const char* ib = smem + IN_OFF + si * IN_STG + rbase;
                char* zt = smem + ST_OFF + si * ST_SLOT + rbase;
                char* st = zt + 2 * TILE_STRIDE;
                #pragma unroll
                for (int tb = 0; tb < 16; tb++) {
                    const uint32_t off = (uint32_t)(tb >> 3) * TILE_STRIDE
                                       + ((uint32_t)((tb & 7) ^ sw) << 4);
                    float4 in4 = *(const float4*)(ib + off);
                    float4 z4, s4;
                    float v_pre; bool spk;
                    v_pre = fmaf(alpha, vv, one_m_alpha * in4.x);
                    z4.x = fmaf(BETA, v_pre, -beta_thr);
                    spk = (v_pre >= thr); s4.x = spk ? 1.0f : 0.0f; vv = spk ? 0.0f : v_pre;
                    v_pre = fmaf(alpha, vv, one_m_alpha * in4.y);
                    z4.y = fmaf(BETA, v_pre, -beta_thr);
                    spk = (v_pre >= thr); s4.y = spk ? 1.0f : 0.0f; vv = spk ? 0.0f : v_pre;
                    v_pre = fmaf(alpha, vv, one_m_alpha * in4.z);
                    z4.z = fmaf(BETA, v_pre, -beta_thr);
                    spk = (v_pre >= thr); s4.z = spk ? 1.0f : 0.0f; vv = spk ? 0.0f : v_pre;
                    v_pre = fmaf(alpha, vv, one_m_alpha * in4.w);
                    z4.w = fmaf(BETA, v_pre, -beta_thr);
                    spk = (v_pre >= thr); s4.w = spk ? 1.0f : 0.0f; vv = spk ? 0.0f : v_pre;
                    *(float4*)(zt + off) = z4;
                    *(float4*)(st + off) = s4;
                }
            }
            mbar_arrive(sb + B_INE(si));      // input stage consumed
            mbar_arrive(sb + B_STF(si));      // z/s tiles written
        }
    } else if (tid == 128) {
        // ===================== TMA-issue thread =====================
        // pre-arm store-slot-free barriers (phase 0 completes: slots empty)
        mbar_arrive(sb + B_STE(0));
        mbar_arrive(sb + B_STE(1));
        // prologue: load input stages 0,1
        #pragma unroll
        for (int s = 0; s < 2; s++) {
            mbar_expect_tx(sb + B_INF(s), tx_bytes);
            const uint32_t dst = sb + IN_OFF + s * IN_STG;
            tma_load_2d(dst,               tin, s * CHUNK,      row0, sb + B_INF(s));
            tma_load_2d(dst + TILE_STRIDE, tin, s * CHUNK + 32, row0, sb + B_INF(s));
        }

        for (int k = 0; k < NCH; k++) {
            const int si = k & 1;
            const uint32_t par = (k >> 1) & 1;
            // refill input stage si with chunk k+2 (prioritize the load stream)
            if (k + 2 < NCH) {
                mbar_wait(sb + B_INE(si), par);          // stage consumed
                mbar_expect_tx(sb + B_INF(si), tx_bytes);
                const uint32_t dst = sb + IN_OFF + si * IN_STG;
                tma_load_2d(dst,               tin, (k + 2) * CHUNK,      row0, sb + B_INF(si));
                tma_load_2d(dst + TILE_STRIDE, tin, (k + 2) * CHUNK + 32, row0, sb + B_INF(si));
            }
            // store chunk k from slot si
            mbar_wait(sb + B_STF(si), par);              // tiles written (acquire)
            asm volatile("fence.proxy.async.shared::cta;" ::: "memory");
            const int t0 = k * CHUNK;
            const uint32_t slot = sb + ST_OFF + si * ST_SLOT;
            tma_store_2d(tz,  t0,      row0, slot);
            tma_store_2d(tz,  t0 + 32, row0, slot + TILE_STRIDE);
            tma_store_2d(tsm, t0,      row0, slot + 2 * TILE_STRIDE);
            tma_store_2d(tsm, t0 + 32, row0, slot + 3 * TILE_STRIDE);
            asm volatile("cp.async.bulk.commit_group;" ::: "memory");
            // group k-1 (slot si^1) drained -> mark that slot free
            if (k >= 1) {
                asm volatile("cp.async.bulk.wait_group 1;" ::: "memory");
                mbar_arrive(sb + B_STE(si ^ 1));
            }
        }
        asm volatile("cp.async.bulk.wait_group 0;" ::: "memory");
    }
}

// ---------------- host side ----------------

typedef CUresult (*EncodeFn)(CUtensorMap*, CUtensorMapDataType, cuuint32_t, void*,
                             const cuuint64_t*, const cuuint64_t*,
                             const cuuint32_t*, const cuuint32_t*,
                             CUtensorMapInterleave, CUtensorMapSwizzle,
                             CUtensorMapL2promotion, CUtensorMapFloatOOBfill);

static void make_map(EncodeFn enc, CUtensorMap* m, void* base, unsigned H) {
    cuuint64_t dims[2]    = {LL, (cuuint64_t)BB * FF};
    cuuint64_t strides[1] = {LL * sizeof(float)};
    cuuint32_t box[2]     = {32, H};
    cuuint32_t es[2]      = {1, 1};
    enc(m, CU_TENSOR_MAP_DATA_TYPE_FLOAT32, 2, base, dims, strides, box, es,
        CU_TENSOR_MAP_INTERLEAVE_NONE, CU_TENSOR_MAP_SWIZZLE_128B,
        CU_TENSOR_MAP_L2_PROMOTION_L2_128B, CU_TENSOR_MAP_FLOAT_OOB_FILL_NONE);
}

extern "C" void kernel_launch(void* const* d_in, const int* in_sizes, int n_in,
                              void* d_out, int out_size)
{
    float* I             = (float*)d_in[0];
    const float* raw_tau = (const float*)d_in[1];
    const float* thr     = (const float*)d_in[2];
    float* out           = (float*)d_out;

    static EncodeFn enc = nullptr;
    if (!enc) {
        cudaDriverEntryPointQueryResult qr;
        void* fp = nullptr;
        cudaGetDriverEntryPoint("cuTensorMapEncodeTiled", &fp,
                                cudaEnableDefault, &qr);
        enc = (EncodeFn)fp;
        cudaFuncSetAttribute(lif_tma_kernel,
                             cudaFuncAttributeMaxDynamicSharedMemorySize, SMEM_BYTES);
    }
    if (!enc) return;

    float* sbase = out + (size_t)BB * FF * LL;
    CUtensorMap in_a, in_b, z_a, z_b, s_a, s_b;
    make_map(enc, &in_a, I, 111);     make_map(enc, &in_b, I, 110);
    make_map(enc, &z_a,  out, 111);   make_map(enc, &z_b,  out, 110);
    make_map(enc, &s_a,  sbase, 111); make_map(enc, &s_b,  sbase, 110);

    lif_tma_kernel<<<148, NTH, SMEM_BYTES>>>(in_a, in_b, z_a, z_b, s_a, s_b,
                                             raw_tau, thr);
}